// round 4
// baseline (speedup 1.0000x reference)
#include <cuda_runtime.h>
#include <cstdint>

#define M_TOTAL 16384
#define K_DIM   2048
#define E_DIM   64
#define TOPK    8

#define BM    128
#define BK    32
#define ASTR  68            // a_sm row stride in floats: 64 dup'd data + 4 pad
#define NTILE (K_DIM / BK)  // 64

// One-time W transpose scratch: Wt[k][e]
__device__ float Wt_g[(size_t)K_DIM * E_DIM];

// Coalesced reads; scattered 4B writes absorbed by L2.
__global__ void transpose_w(const float* __restrict__ W, float* __restrict__ Wt) {
    int t = blockIdx.x * blockDim.x + threadIdx.x;   // 131072
    int e = t >> 11;            // 0..63
    int k = t & (K_DIM - 1);    // 0..2047
    Wt[(size_t)k * E_DIM + e] = W[(size_t)e * K_DIM + k];
}

// Packed fp32x2 FMA; per-lane rounding identical to scalar fmaf.
__device__ __forceinline__ float2 ffma2(float2 a, float2 b, float2 c) {
    float2 d;
    asm("fma.rn.f32x2 %0, %1, %2, %3;"
        : "=l"(reinterpret_cast<unsigned long long&>(d))
        : "l"(reinterpret_cast<unsigned long long&>(a)),
          "l"(reinterpret_cast<unsigned long long&>(b)),
          "l"(reinterpret_cast<unsigned long long&>(c)));
    return d;
}

// Fused logits GEMM (sequential-k FMA chain per (m,e)) + top-8 + softmax.
// __launch_bounds__(256,2): cap regs at 128 so 2 CTAs co-reside per SM
// (16 warps) — hides sync/latency bubbles that bounded round 3 at occ 12%.
__global__ __launch_bounds__(256, 2)
void router_fused(const float* __restrict__ X, const float* __restrict__ Wt,
                  float* __restrict__ logits,
                  float* __restrict__ wout, float* __restrict__ eout) {
    __shared__ float smem[BM * ASTR + BK * E_DIM];   // 42 KB static
    float* a_sm = smem;                // [BM][ASTR], dup'd pairs
    float* b_sm = smem + BM * ASTR;    // [BK][E_DIM]

    const int tid = threadIdx.x;
    const int eg  = tid & 7;
    const int mg  = tid >> 3;
    const int m0  = blockIdx.x * BM;

    float2 acc[4][4];
    #pragma unroll
    for (int i = 0; i < 4; i++)
        #pragma unroll
        for (int j = 0; j < 4; j++) acc[i][j] = make_float2(0.f, 0.f);

    float4 pa[4];
    float4 pb[2];

    int arow[4], aq[4];
    #pragma unroll
    for (int i = 0; i < 4; i++) { int f = tid + i * 256; arow[i] = f >> 3; aq[i] = f & 7; }

    #pragma unroll
    for (int i = 0; i < 4; i++)
        pa[i] = *reinterpret_cast<const float4*>(&X[(size_t)(m0 + arow[i]) * K_DIM + aq[i] * 4]);
    {
        const float4* src = reinterpret_cast<const float4*>(Wt);
        pb[0] = src[tid];
        pb[1] = src[tid + 256];
    }

    for (int t = 0; t < NTILE; t++) {
        #pragma unroll
        for (int i = 0; i < 4; i++) {
            float4 v = pa[i];
            *reinterpret_cast<float4*>(&a_sm[arow[i] * ASTR + aq[i] * 8]) =
                make_float4(v.x, v.x, v.y, v.y);
            *reinterpret_cast<float4*>(&a_sm[arow[i] * ASTR + aq[i] * 8 + 4]) =
                make_float4(v.z, v.z, v.w, v.w);
        }
        {
            float4* dst = reinterpret_cast<float4*>(b_sm);
            dst[tid]       = pb[0];
            dst[tid + 256] = pb[1];
        }
        __syncthreads();

        if (t + 1 < NTILE) {
            int kn = (t + 1) * BK;
            #pragma unroll
            for (int i = 0; i < 4; i++)
                pa[i] = *reinterpret_cast<const float4*>(
                    &X[(size_t)(m0 + arow[i]) * K_DIM + kn + aq[i] * 4]);
            const float4* src = reinterpret_cast<const float4*>(&Wt[(size_t)kn * E_DIM]);
            pb[0] = src[tid];
            pb[1] = src[tid + 256];
        }

        #pragma unroll
        for (int kk = 0; kk < BK; kk += 2) {
            float4 a4[4];
            #pragma unroll
            for (int i = 0; i < 4; i++)
                a4[i] = *reinterpret_cast<const float4*>(&a_sm[(mg * 4 + i) * ASTR + kk * 2]);

            #pragma unroll
            for (int s = 0; s < 2; s++) {
                float4 b0 = *reinterpret_cast<const float4*>(&b_sm[(kk + s) * E_DIM + eg * 4]);
                float4 b1 = *reinterpret_cast<const float4*>(&b_sm[(kk + s) * E_DIM + eg * 4 + 32]);
                float2 bp0 = make_float2(b0.x, b0.y);
                float2 bp1 = make_float2(b0.z, b0.w);
                float2 bp2 = make_float2(b1.x, b1.y);
                float2 bp3 = make_float2(b1.z, b1.w);
                #pragma unroll
                for (int i = 0; i < 4; i++) {
                    float2 ap = s ? make_float2(a4[i].z, a4[i].w)
                                  : make_float2(a4[i].x, a4[i].y);
                    acc[i][0] = ffma2(ap, bp0, acc[i][0]);
                    acc[i][1] = ffma2(ap, bp1, acc[i][1]);
                    acc[i][2] = ffma2(ap, bp2, acc[i][2]);
                    acc[i][3] = ffma2(ap, bp3, acc[i][3]);
                }
            }
        }
        __syncthreads();
    }

    // Epilogue: write logits + stage rows in smem for topk.
    #pragma unroll
    for (int i = 0; i < 4; i++) {
        int m = mg * 4 + i;
        float4 lo = make_float4(acc[i][0].x, acc[i][0].y, acc[i][1].x, acc[i][1].y);
        float4 hi = make_float4(acc[i][2].x, acc[i][2].y, acc[i][3].x, acc[i][3].y);
        *reinterpret_cast<float4*>(&logits[(size_t)(m0 + m) * E_DIM + eg * 4])      = lo;
        *reinterpret_cast<float4*>(&logits[(size_t)(m0 + m) * E_DIM + eg * 4 + 32]) = hi;
        *reinterpret_cast<float4*>(&smem[m * ASTR + eg * 4])      = lo;
        *reinterpret_cast<float4*>(&smem[m * ASTR + eg * 4 + 32]) = hi;
    }
    __syncthreads();

    // Top-8 + softmax: one thread per token.
    if (tid < BM) {
        const float* row = &smem[tid * ASTR];
        float tv[TOPK];
        int   ti[TOPK];
        #pragma unroll
        for (int i = 0; i < TOPK; i++) { tv[i] = -3.4e38f; ti[i] = 0; }

        #pragma unroll
        for (int q = 0; q < E_DIM / 4; q++) {
            float4 v4 = *reinterpret_cast<const float4*>(&row[q * 4]);
            float vs[4] = {v4.x, v4.y, v4.z, v4.w};
            #pragma unroll
            for (int u = 0; u < 4; u++) {
                float v = vs[u];
                int   e = q * 4 + u;
                if (v > tv[TOPK - 1]) {
                    tv[TOPK - 1] = v; ti[TOPK - 1] = e;
                    #pragma unroll
                    for (int j = TOPK - 1; j > 0; j--) {
                        if (tv[j] > tv[j - 1]) {
                            float tf = tv[j]; tv[j] = tv[j - 1]; tv[j - 1] = tf;
                            int   tx = ti[j]; ti[j] = ti[j - 1]; ti[j - 1] = tx;
                        }
                    }
                }
            }
        }

        float mx = tv[0];
        float ev[TOPK], ssum = 0.f;
        #pragma unroll
        for (int i = 0; i < TOPK; i++) { ev[i] = __expf(tv[i] - mx); ssum += ev[i]; }
        float inv = 1.f / ssum;
        size_t tok = (size_t)(m0 + tid);
        #pragma unroll
        for (int i = 0; i < TOPK; i++) {
            wout[tok * TOPK + i] = ev[i] * inv;
            eout[tok * TOPK + i] = (float)ti[i];
        }
    }
}

extern "C" void kernel_launch(void* const* d_in, const int* in_sizes, int n_in,
                              void* d_out, int out_size) {
    const float* X = (const float*)d_in[0];   // [4,4096,2048] fp32
    const float* W = (const float*)d_in[1];   // [64,2048]     fp32

    float* out    = (float*)d_out;
    float* logits = out;                                   // 16384*64
    float* wts    = out + (size_t)M_TOTAL * E_DIM;         // 16384*8
    float* exps   = wts + (size_t)M_TOTAL * TOPK;          // 16384*8

    float* Wt;
    cudaGetSymbolAddress((void**)&Wt, Wt_g);

    transpose_w<<<(K_DIM * E_DIM) / 256, 256>>>(W, Wt);
    router_fused<<<M_TOTAL / BM, 256>>>(X, Wt, logits, wts, exps);
}